// round 2
// baseline (speedup 1.0000x reference)
#include <cuda_runtime.h>

#define N_NODES 32
#define D_EMB   96
#define N_EDGES 256
#define P_PAIRS 1024
#define M_TOT   262144   // P_PAIRS * N_EDGES

// ---- scratch (device globals: no allocations allowed) ----
__device__ float g_G[16 * M_TOT];       // conv features, layout [feature][sample]
__device__ float g_preds[M_TOT];        // masked MLP outputs, [p*256 + e]
__device__ float g_part[P_PAIRS * 32];  // per-p rbc partials

// ---- packed f32x2 helpers (FFMA2 path, sm_100+) ----
__device__ __forceinline__ unsigned long long pack2(float lo, float hi) {
    unsigned long long r;
    asm("mov.b64 %0, {%1, %2};" : "=l"(r) : "f"(lo), "f"(hi));
    return r;
}
__device__ __forceinline__ void unpack2(unsigned long long v, float& lo, float& hi) {
    asm("mov.b64 {%0, %1}, %2;" : "=f"(lo), "=f"(hi) : "l"(v));
}
__device__ __forceinline__ unsigned long long fma2(unsigned long long a,
                                                   unsigned long long b,
                                                   unsigned long long c) {
    unsigned long long d;
    asm("fma.rn.f32x2 %0, %1, %2, %3;" : "=l"(d) : "l"(a), "l"(b), "l"(c));
    return d;
}

// =====================================================================
// Kernel 1: conv stack (thread per sample). 4x96 input -> 16 features.
// =====================================================================
__global__ void __launch_bounds__(256) conv_kernel(
    const float* __restrict__ emb, const int* __restrict__ edges,
    const float* __restrict__ w1, const float* __restrict__ b1,
    const float* __restrict__ w2, const float* __restrict__ b2,
    const float* __restrict__ w3, const float* __restrict__ b3)
{
    __shared__ float semb[N_NODES * D_EMB];
    __shared__ float sw1[48], sw2[48], sw3[48];
    __shared__ float sb1[4], sb2[4], sb3[4];
    int tid = threadIdx.x;
    for (int i = tid; i < N_NODES * D_EMB; i += 256) semb[i] = emb[i];
    if (tid < 48) { sw1[tid] = w1[tid]; sw2[tid] = w2[tid]; sw3[tid] = w3[tid]; }
    if (tid < 4)  { sb1[tid] = b1[tid]; sb2[tid] = b2[tid]; sb3[tid] = b3[tid]; }
    __syncthreads();

    int m = blockIdx.x * 256 + tid;
    int p = m >> 8, e = m & 255;
    int s = p >> 5, t = p & 31;
    int u = edges[2 * e], v = edges[2 * e + 1];
    const float* Xp[4] = { semb + s * D_EMB, semb + t * D_EMB,
                           semb + u * D_EMB, semb + v * D_EMB };

    // conv1 (k=3, stride 2, L 96->47) + relu + pool2 -> 23
    float p1[4][23];
    #pragma unroll
    for (int i = 0; i < 23; i++) {
        float xw[4][5];
        #pragma unroll
        for (int c = 0; c < 4; c++)
            #pragma unroll
            for (int q = 0; q < 5; q++) xw[c][q] = Xp[c][4 * i + q];
        #pragma unroll
        for (int o = 0; o < 4; o++) {
            float a0 = sb1[o], a1 = sb1[o];
            #pragma unroll
            for (int c = 0; c < 4; c++)
                #pragma unroll
                for (int k = 0; k < 3; k++) {
                    float wv = sw1[(o * 4 + c) * 3 + k];
                    a0 = fmaf(wv, xw[c][k],     a0);
                    a1 = fmaf(wv, xw[c][k + 2], a1);
                }
            p1[o][i] = fmaxf(fmaxf(a0, a1), 0.0f);  // relu(max) == max(relu)
        }
    }

    // conv2 (stride 1, 23->21) + relu + pool2 -> 10
    float p2[4][10];
    #pragma unroll
    for (int i = 0; i < 10; i++) {
        #pragma unroll
        for (int o = 0; o < 4; o++) {
            float a0 = sb2[o], a1 = sb2[o];
            #pragma unroll
            for (int c = 0; c < 4; c++)
                #pragma unroll
                for (int k = 0; k < 3; k++) {
                    float wv = sw2[(o * 4 + c) * 3 + k];
                    a0 = fmaf(wv, p1[c][2 * i + k],     a0);
                    a1 = fmaf(wv, p1[c][2 * i + 1 + k], a1);
                }
            p2[o][i] = fmaxf(fmaxf(a0, a1), 0.0f);
        }
    }

    // conv3 (10->8) + relu + pool2 -> 4; flatten [o*4 + pos]
    #pragma unroll
    for (int pos = 0; pos < 4; pos++) {
        #pragma unroll
        for (int o = 0; o < 4; o++) {
            float a0 = sb3[o], a1 = sb3[o];
            #pragma unroll
            for (int c = 0; c < 4; c++)
                #pragma unroll
                for (int k = 0; k < 3; k++) {
                    float wv = sw3[(o * 4 + c) * 3 + k];
                    a0 = fmaf(wv, p2[c][2 * pos + k],     a0);
                    a1 = fmaf(wv, p2[c][2 * pos + 1 + k], a1);
                }
            float g = fmaxf(fmaxf(a0, a1), 0.0f);
            g_G[(o * 4 + pos) * M_TOT + m] = g;   // coalesced per warp
        }
    }
}

// =====================================================================
// Kernel 2: fused FC chain. Block = 128-sample tile, 256 threads.
// smem: A3T (256x128 = 128KB) | A2T (128x128 = 64KB) | WS (16x128 = 8KB)
// Activations stored transposed [k][m] for conflict-free float4 LDS.
// Inner product uses packed fma.rn.f32x2 (FFMA2): 2x FMA-pipe throughput.
// =====================================================================
#define SMEM_A2T_OFF 32768
#define SMEM_WS_OFF  49152
#define SMEM_FLOATS  51200   // 204800 bytes

template<int K>
__device__ __forceinline__ void gemm_phase(
    const float* __restrict__ As,   // smem [K][128]
    const float* __restrict__ Wg,   // global, row-major [K][wstride]
    int wstride, int ncol0,
    const float* __restrict__ bias, // global bias (offset by ncol0)
    float* Out,                     // smem [n][128] (caller pre-offset)
    float* WS, int tid)
{
    const int tm = tid & 15, tn = tid >> 4;  // 16 x 16 threads, tile 8m x 8n
    unsigned long long acc[8][4];            // [i][jpair], packed f32x2
    #pragma unroll
    for (int i = 0; i < 8; i++)
        #pragma unroll
        for (int j2 = 0; j2 < 4; j2++) acc[i][j2] = 0ull;

    for (int kt = 0; kt < K; kt += 16) {
        __syncthreads();  // protect WS reuse + As producer visibility
        for (int idx = tid; idx < 2048; idx += 256) {
            int kk = idx >> 7, nn = idx & 127;
            WS[idx] = Wg[(kt + kk) * wstride + ncol0 + nn];
        }
        __syncthreads();
        #pragma unroll 4
        for (int kk = 0; kk < 16; kk++) {
            const float4* ap = (const float4*)(As + (kt + kk) * 128 + tm * 8);
            float4 a0 = ap[0], a1 = ap[1];
            const float4* wp = (const float4*)(WS + kk * 128 + tn * 8);
            float4 w0 = wp[0], w1 = wp[1];
            unsigned long long ad[8];
            ad[0] = pack2(a0.x, a0.x); ad[1] = pack2(a0.y, a0.y);
            ad[2] = pack2(a0.z, a0.z); ad[3] = pack2(a0.w, a0.w);
            ad[4] = pack2(a1.x, a1.x); ad[5] = pack2(a1.y, a1.y);
            ad[6] = pack2(a1.z, a1.z); ad[7] = pack2(a1.w, a1.w);
            unsigned long long wv[4];
            wv[0] = pack2(w0.x, w0.y); wv[1] = pack2(w0.z, w0.w);
            wv[2] = pack2(w1.x, w1.y); wv[3] = pack2(w1.z, w1.w);
            #pragma unroll
            for (int i = 0; i < 8; i++)
                #pragma unroll
                for (int j2 = 0; j2 < 4; j2++)
                    acc[i][j2] = fma2(ad[i], wv[j2], acc[i][j2]);
        }
    }
    // unpack accumulators into scalar tile
    float cacc[8][8];
    #pragma unroll
    for (int i = 0; i < 8; i++)
        #pragma unroll
        for (int j2 = 0; j2 < 4; j2++)
            unpack2(acc[i][j2], cacc[i][2 * j2], cacc[i][2 * j2 + 1]);

    __syncthreads();
    #pragma unroll
    for (int j = 0; j < 8; j++) {
        float bj = bias[ncol0 + tn * 8 + j];
        float4 o0, o1;
        o0.x = fmaxf(cacc[0][j] + bj, 0.0f);
        o0.y = fmaxf(cacc[1][j] + bj, 0.0f);
        o0.z = fmaxf(cacc[2][j] + bj, 0.0f);
        o0.w = fmaxf(cacc[3][j] + bj, 0.0f);
        o1.x = fmaxf(cacc[4][j] + bj, 0.0f);
        o1.y = fmaxf(cacc[5][j] + bj, 0.0f);
        o1.z = fmaxf(cacc[6][j] + bj, 0.0f);
        o1.w = fmaxf(cacc[7][j] + bj, 0.0f);
        float4* op = (float4*)(Out + (tn * 8 + j) * 128 + tm * 8);
        op[0] = o0; op[1] = o1;
    }
}

__global__ void __launch_bounds__(256) fc_kernel(
    const float* __restrict__ fc1w, const float* __restrict__ fc1b,
    const float* __restrict__ fc2w, const float* __restrict__ fc2b,
    const float* __restrict__ fc3w, const float* __restrict__ fc3b,
    const float* __restrict__ fc4w, const float* __restrict__ fc4b)
{
    extern __shared__ float sm[];
    float* A3T = sm;                  // also hosts GT [16][128] initially
    float* A2T = sm + SMEM_A2T_OFF;
    float* WS  = sm + SMEM_WS_OFF;
    int tid = threadIdx.x;
    int m0 = blockIdx.x * 128;

    // stage conv features GT[k][mm]
    for (int idx = tid; idx < 16 * 128; idx += 256) {
        int k = idx >> 7, mm = idx & 127;
        A3T[idx] = g_G[k * M_TOT + m0 + mm];
    }
    __syncthreads();

    gemm_phase<16 >(A3T, fc1w, 128, 0,   fc1b, A2T,             WS, tid); // fc1: GT->A2T
    gemm_phase<128>(A2T, fc2w, 256, 0,   fc2b, A3T,             WS, tid); // fc2 n[0,128)
    gemm_phase<128>(A2T, fc2w, 256, 128, fc2b, A3T + 128 * 128, WS, tid); // fc2 n[128,256)
    gemm_phase<256>(A3T, fc3w, 128, 0,   fc3b, A2T,             WS, tid); // fc3 -> A4T(=A2T)
    __syncthreads();

    // fc4: out[m] = sum_k A4T[k][m] * w4[k] + b4, split K over 2 halves
    int mm = tid & 127, half = tid >> 7;
    float ssum = 0.0f;
    #pragma unroll 8
    for (int k = half * 64; k < half * 64 + 64; k++)
        ssum = fmaf(A2T[k * 128 + mm], fc4w[k], ssum);
    WS[half * 128 + mm] = ssum;
    __syncthreads();
    if (tid < 128) {
        float r = WS[tid] + WS[128 + tid] + fc4b[0];
        int m = m0 + tid;
        int p = m >> 8;
        if ((p >> 5) == (p & 31)) r = 0.0f;   // mask s==t rows
        g_preds[m] = r;
    }
}

// =====================================================================
// Kernel 3: 3-step propagation, block per p. Deterministic (no atomics).
// =====================================================================
__global__ void __launch_bounds__(256) prop_kernel(const int* __restrict__ edges)
{
    __shared__ float xs[32];
    __shared__ float xn[8][32];
    __shared__ float acc[32];
    __shared__ float pr[256];
    __shared__ int   su[256], sv[256];
    int tid = threadIdx.x;
    int p = blockIdx.x;
    int s = p >> 5, t = p & 31;
    pr[tid] = g_preds[p * 256 + tid];
    su[tid] = edges[2 * tid];
    sv[tid] = edges[2 * tid + 1];
    if (tid < 32) { xs[tid] = (tid == s) ? 1.0f : 0.0f; acc[tid] = 0.0f; }
    __syncthreads();
    if (s != t) {
        int j = tid & 31, grp = tid >> 5;
        for (int step = 0; step < 3; step++) {
            float sum = 0.0f;
            #pragma unroll 4
            for (int q = 0; q < 32; q++) {
                int e = grp * 32 + q;
                sum += (sv[e] == j) ? xs[su[e]] * pr[e] : 0.0f;
            }
            xn[grp][j] = sum;
            __syncthreads();
            if (tid < 32) {
                float v = 0.0f;
                #pragma unroll
                for (int g2 = 0; g2 < 8; g2++) v += xn[g2][tid];
                xs[tid] = v;
                acc[tid] += v;
            }
            __syncthreads();
        }
    }
    if (tid < 32) g_part[p * 32 + tid] = acc[tid];
}

// =====================================================================
// Kernel 4: final reduction + normalize (single block, deterministic).
// =====================================================================
__global__ void __launch_bounds__(1024) reduce_kernel(float* __restrict__ out)
{
    __shared__ float red[32][32];
    __shared__ float rbc[32];
    __shared__ float tot;
    int tid = threadIdx.x;
    int j = tid & 31, chunk = tid >> 5;
    float sum = 0.0f;
    for (int q = 0; q < 32; q++)
        sum += g_part[(chunk * 32 + q) * 32 + j];
    red[chunk][j] = sum;
    __syncthreads();
    if (tid < 32) {
        float v = 0.0f;
        for (int c = 0; c < 32; c++) v += red[c][tid];
        rbc[tid] = v;
    }
    __syncthreads();
    if (tid == 0) {
        float tt = 0.0f;
        for (int k = 0; k < 32; k++) tt += rbc[k];
        tot = tt;
    }
    __syncthreads();
    if (tid < 32) out[tid] = rbc[tid] / tot;
}

// =====================================================================
extern "C" void kernel_launch(void* const* d_in, const int* in_sizes, int n_in,
                              void* d_out, int out_size)
{
    const float* emb   = (const float*)d_in[0];
    const int*   edges = (const int*)  d_in[1];
    const float* w1    = (const float*)d_in[2];
    const float* b1    = (const float*)d_in[3];
    const float* w2    = (const float*)d_in[4];
    const float* b2    = (const float*)d_in[5];
    const float* w3    = (const float*)d_in[6];
    const float* b3    = (const float*)d_in[7];
    const float* fc1w  = (const float*)d_in[8];
    const float* fc1b  = (const float*)d_in[9];
    const float* fc2w  = (const float*)d_in[10];
    const float* fc2b  = (const float*)d_in[11];
    const float* fc3w  = (const float*)d_in[12];
    const float* fc3b  = (const float*)d_in[13];
    const float* fc4w  = (const float*)d_in[14];
    const float* fc4b  = (const float*)d_in[15];

    conv_kernel<<<M_TOT / 256, 256>>>(emb, edges, w1, b1, w2, b2, w3, b3);

    size_t smem_bytes = SMEM_FLOATS * sizeof(float);  // 204800 B (opt-in)
    cudaFuncSetAttribute(fc_kernel, cudaFuncAttributeMaxDynamicSharedMemorySize,
                         (int)smem_bytes);
    fc_kernel<<<M_TOT / 128, 256, smem_bytes>>>(fc1w, fc1b, fc2w, fc2b,
                                                fc3w, fc3b, fc4w, fc4b);

    prop_kernel<<<P_PAIRS, 256>>>(edges);
    reduce_kernel<<<1, 1024>>>((float*)d_out);
}

// round 4
// speedup vs baseline: 1.9876x; 1.9876x over previous
#include <cuda_runtime.h>
#include <cuda_bf16.h>
#include <cstdint>

#define N_NODES 32
#define D_EMB   96
#define P_PAIRS 1024
#define M_TOT   262144   // P_PAIRS * 256

// ---- scratch (device globals: no allocations allowed) ----
__device__ float g_G[16 * M_TOT];       // conv features [feature][sample]
__device__ float g_preds[M_TOT];
__device__ float g_part[P_PAIRS * 32];
// weight images: bf16 hi/lo, pre-transposed [n][k], pre-swizzled (W2/W3)
__device__ __align__(16) __nv_bfloat16 g_W1[6144];    // [n=128][kp=24] hi | lo
__device__ __align__(16) __nv_bfloat16 g_W2[131072];  // (h,c) chunks: [128n][64k] hi | lo
__device__ __align__(16) __nv_bfloat16 g_W3[65536];   // [128n][256k] hi | lo

// ---------------- helpers ----------------
__device__ __forceinline__ uint32_t smem_u32(const void* p) {
    uint32_t a;
    asm("{ .reg .u64 t; cvta.to.shared.u64 t, %1; cvt.u32.u64 %0, t; }" : "=r"(a) : "l"(p));
    return a;
}
__device__ __forceinline__ uint32_t swz(int m, int kb, int rowb) {
    return (uint32_t)(m * rowb + (kb ^ ((m & 7) << 4)));
}
__device__ __forceinline__ void ldsm4(uint32_t a, uint32_t* r) {
    asm volatile("ldmatrix.sync.aligned.m8n8.x4.shared.b16 {%0,%1,%2,%3}, [%4];"
        : "=r"(r[0]), "=r"(r[1]), "=r"(r[2]), "=r"(r[3]) : "r"(a));
}
__device__ __forceinline__ void mma16816(float* c, const uint32_t* a, uint32_t b0, uint32_t b1) {
    asm volatile("mma.sync.aligned.m16n8k16.row.col.f32.bf16.bf16.f32 "
        "{%0,%1,%2,%3}, {%4,%5,%6,%7}, {%8,%9}, {%0,%1,%2,%3};"
        : "+f"(c[0]), "+f"(c[1]), "+f"(c[2]), "+f"(c[3])
        : "r"(a[0]), "r"(a[1]), "r"(a[2]), "r"(a[3]), "r"(b0), "r"(b1));
}
__device__ __forceinline__ void bsplit(float x, __nv_bfloat16& h, __nv_bfloat16& l) {
    h = __float2bfloat16_rn(x);
    l = __float2bfloat16_rn(x - __bfloat162float(h));
}
__device__ __forceinline__ uint32_t pk(__nv_bfloat16 lo, __nv_bfloat16 hi) {
    return (uint32_t)__bfloat16_as_ushort(hi) << 16 | (uint32_t)__bfloat16_as_ushort(lo);
}
__device__ __forceinline__ void sts32(uint32_t addr, uint32_t v) {
    asm volatile("st.shared.b32 [%0], %1;" :: "r"(addr), "r"(v) : "memory");
}
__device__ __forceinline__ void copyg(void* dst, const __nv_bfloat16* src, int bytes, int tid) {
    float4* d = (float4*)dst; const float4* s = (const float4*)src;
    for (int i = tid; i < (bytes >> 4); i += 256) d[i] = s[i];
}

// =====================================================================
// Kernel 0: prep — split weights to bf16 hi/lo images
// =====================================================================
__global__ void __launch_bounds__(256) prep_kernel(
    const float* __restrict__ fc1w, const float* __restrict__ fc2w,
    const float* __restrict__ fc3w)
{
    int idx = blockIdx.x * 256 + threadIdx.x;   // 0 .. 68607
    float val; int ph, pl;
    if (idx < 3072) {                 // W1: [n=128][kp=24], linear (padded)
        int n = idx / 24, k = idx % 24;
        val = (k < 16) ? fc1w[k * 128 + n] : 0.0f;
        ph = n * 24 + k; pl = 3072 + ph;
    } else if (idx < 35840) {         // W2: (h,c) chunks [128n][64k] swizzled rowb=128
        int j = idx - 3072;
        int h = j >> 14, c = (j >> 13) & 1;
        int j2 = j & 8191;
        int n = j2 >> 6, k = j2 & 63;
        val = fc2w[(c * 64 + k) * 256 + h * 128 + n];
        int eo = n * 64 + (((k * 2) ^ ((n & 7) << 4)) >> 1);
        ph = (h * 2 + c) * 16384 + eo; pl = ph + 8192;
        __nv_bfloat16 hh, ll; bsplit(val, hh, ll);
        g_W2[ph] = hh; g_W2[pl] = ll;
        return;
    } else {                          // W3: [128n][256k] swizzled rowb=512
        int j = idx - 35840;
        int n = j >> 8, k = j & 255;
        val = fc3w[k * 128 + n];
        int eo = n * 256 + (((k * 2) ^ ((n & 7) << 4)) >> 1);
        ph = eo; pl = 32768 + eo;
        __nv_bfloat16 hh, ll; bsplit(val, hh, ll);
        g_W3[ph] = hh; g_W3[pl] = ll;
        return;
    }
    __nv_bfloat16 hh, ll; bsplit(val, hh, ll);
    g_W1[ph] = hh; g_W1[pl] = ll;
}

// =====================================================================
// Kernel 1: conv stack (thread per sample). 4x96 input -> 16 features.
// =====================================================================
__global__ void __launch_bounds__(256) conv_kernel(
    const float* __restrict__ emb, const int* __restrict__ edges,
    const float* __restrict__ w1, const float* __restrict__ b1,
    const float* __restrict__ w2, const float* __restrict__ b2,
    const float* __restrict__ w3, const float* __restrict__ b3)
{
    __shared__ float semb[N_NODES * D_EMB];
    __shared__ float sw1[48], sw2[48], sw3[48];
    __shared__ float sb1[4], sb2[4], sb3[4];
    int tid = threadIdx.x;
    for (int i = tid; i < N_NODES * D_EMB; i += 256) semb[i] = emb[i];
    if (tid < 48) { sw1[tid] = w1[tid]; sw2[tid] = w2[tid]; sw3[tid] = w3[tid]; }
    if (tid < 4)  { sb1[tid] = b1[tid]; sb2[tid] = b2[tid]; sb3[tid] = b3[tid]; }
    __syncthreads();

    int m = blockIdx.x * 256 + tid;
    int p = m >> 8, e = m & 255;
    int s = p >> 5, t = p & 31;
    int u = edges[2 * e], v = edges[2 * e + 1];
    const float* Xp[4] = { semb + s * D_EMB, semb + t * D_EMB,
                           semb + u * D_EMB, semb + v * D_EMB };

    float p1[4][23];
    #pragma unroll
    for (int i = 0; i < 23; i++) {
        float xw[4][5];
        #pragma unroll
        for (int c = 0; c < 4; c++)
            #pragma unroll
            for (int q = 0; q < 5; q++) xw[c][q] = Xp[c][4 * i + q];
        #pragma unroll
        for (int o = 0; o < 4; o++) {
            float a0 = sb1[o], a1 = sb1[o];
            #pragma unroll
            for (int c = 0; c < 4; c++)
                #pragma unroll
                for (int k = 0; k < 3; k++) {
                    float wv = sw1[(o * 4 + c) * 3 + k];
                    a0 = fmaf(wv, xw[c][k],     a0);
                    a1 = fmaf(wv, xw[c][k + 2], a1);
                }
            p1[o][i] = fmaxf(fmaxf(a0, a1), 0.0f);
        }
    }
    float p2[4][10];
    #pragma unroll
    for (int i = 0; i < 10; i++) {
        #pragma unroll
        for (int o = 0; o < 4; o++) {
            float a0 = sb2[o], a1 = sb2[o];
            #pragma unroll
            for (int c = 0; c < 4; c++)
                #pragma unroll
                for (int k = 0; k < 3; k++) {
                    float wv = sw2[(o * 4 + c) * 3 + k];
                    a0 = fmaf(wv, p1[c][2 * i + k],     a0);
                    a1 = fmaf(wv, p1[c][2 * i + 1 + k], a1);
                }
            p2[o][i] = fmaxf(fmaxf(a0, a1), 0.0f);
        }
    }
    #pragma unroll
    for (int pos = 0; pos < 4; pos++) {
        #pragma unroll
        for (int o = 0; o < 4; o++) {
            float a0 = sb3[o], a1 = sb3[o];
            #pragma unroll
            for (int c = 0; c < 4; c++)
                #pragma unroll
                for (int k = 0; k < 3; k++) {
                    float wv = sw3[(o * 4 + c) * 3 + k];
                    a0 = fmaf(wv, p2[c][2 * pos + k],     a0);
                    a1 = fmaf(wv, p2[c][2 * pos + 1 + k], a1);
                }
            g_G[(o * 4 + pos) * M_TOT + m] = fmaxf(fmaxf(a0, a1), 0.0f);
        }
    }
}

// =====================================================================
// Kernel 2: fused FC chain on HMMA (mma.sync bf16, 3-term split).
// CTA = 256 threads (8 warps), M-tile 128. warp tile = 32m x 64n.
// smem map (bytes):
//   OFF_A2  = 0      : 65536  A2hi|A2lo (rowb 256)  -> reused as W3 stage
//   OFF_A3  = 65536  : 131072 A3hi|A3lo (rowb 512); hosts A1+W1 at start
//   OFF_WST = 196608 : 32768  W2 chunk hi|lo (rowb 128); reused as red buf
// =====================================================================
#define OFF_A2  0
#define OFF_A3  65536
#define OFF_WST 196608
#define FC_SMEM 229376

__device__ __forceinline__ void zero_acc(float acc[2][8][4]) {
    #pragma unroll
    for (int i = 0; i < 2; i++)
        #pragma unroll
        for (int j = 0; j < 8; j++)
            #pragma unroll
            for (int q = 0; q < 4; q++) acc[i][j][q] = 0.f;
}
__device__ __forceinline__ void mma_tile(float acc[2][8][4],
                                         uint32_t a[2][4], uint32_t b[4][4]) {
    #pragma unroll
    for (int i = 0; i < 2; i++)
        #pragma unroll
        for (int p = 0; p < 4; p++) {
            mma16816(acc[i][2 * p],     a[i], b[p][0], b[p][1]);
            mma16816(acc[i][2 * p + 1], a[i], b[p][2], b[p][3]);
        }
}
__device__ __forceinline__ void load_afrag(uint32_t base, int mb, int kb0, int rowb,
                                           int mi, int r8, uint32_t a[2][4]) {
    #pragma unroll
    for (int i = 0; i < 2; i++) {
        int m = mb + i * 16 + r8 + ((mi & 1) << 3);
        int kb = kb0 + ((mi >> 1) << 4);
        ldsm4(base + swz(m, kb, rowb), a[i]);
    }
}
__device__ __forceinline__ void load_bfrag(uint32_t base, int nb, int kb0, int rowb,
                                           int mi, int r8, uint32_t b[4][4]) {
    #pragma unroll
    for (int p = 0; p < 4; p++) {
        int n = nb + p * 16 + r8 + ((mi >> 1) << 3);
        int kb = kb0 + ((mi & 1) << 4);
        ldsm4(base + swz(n, kb, rowb), b[p]);
    }
}
__device__ __forceinline__ void store_pair(uint32_t hib, uint32_t lob, int m, int col,
                                           int rowb, float v0, float v1) {
    __nv_bfloat16 h0, l0, h1, l1;
    bsplit(v0, h0, l0); bsplit(v1, h1, l1);
    uint32_t off = swz(m, col * 2, rowb);
    sts32(hib + off, pk(h0, h1));
    sts32(lob + off, pk(l0, l1));
}
__device__ __forceinline__ void epilogue_act(float acc[2][8][4],
    uint32_t hib, uint32_t lob, int rowb, int mb, int nb, int kofs,
    const float* __restrict__ bias, int r4, int c4)
{
    #pragma unroll
    for (int i = 0; i < 2; i++)
        #pragma unroll
        for (int j = 0; j < 8; j++) {
            int col = nb + j * 8 + c4 * 2;
            int dc = kofs + col;
            float b0 = __ldg(bias + dc), b1 = __ldg(bias + dc + 1);
            int m = mb + i * 16 + r4;
            store_pair(hib, lob, m, dc, rowb,
                       fmaxf(acc[i][j][0] + b0, 0.f), fmaxf(acc[i][j][1] + b1, 0.f));
            store_pair(hib, lob, m + 8, dc, rowb,
                       fmaxf(acc[i][j][2] + b0, 0.f), fmaxf(acc[i][j][3] + b1, 0.f));
        }
}

__global__ void __launch_bounds__(256) fc_kernel(
    const float* __restrict__ fc1b, const float* __restrict__ fc2b,
    const float* __restrict__ fc3b, const float* __restrict__ fc4w,
    const float* __restrict__ fc4b)
{
    extern __shared__ char sm[];
    const uint32_t smb = smem_u32(sm);
    const int tid = threadIdx.x;
    const int l = tid & 31, w = tid >> 5;
    const int wm = w & 3, wn = w >> 2;
    const int mb = wm * 32, nb = wn * 64;
    const int m0 = blockIdx.x * 128;
    const int mi = l >> 3, r8 = l & 7;
    const int r4 = l >> 2, c4 = l & 3;

    const uint32_t A1h = smb + OFF_A3, A1l = A1h + 6144;
    const uint32_t W1h = A1h + 12288, W1l = A1h + 18432;
    const uint32_t A2h = smb + OFF_A2, A2l = A2h + 32768;
    const uint32_t A3h = smb + OFF_A3, A3l = A3h + 65536;
    const uint32_t WST = smb + OFF_WST;

    // ---- stage A1 (from g_G, padded kp=24) + W1 ----
    {
        __nv_bfloat16* a1h = (__nv_bfloat16*)(sm + OFF_A3);
        __nv_bfloat16* a1l = (__nv_bfloat16*)(sm + OFF_A3 + 6144);
        for (int idx = tid; idx < 2048; idx += 256) {
            int k = idx >> 7, m = idx & 127;
            float v = g_G[k * M_TOT + m0 + m];
            __nv_bfloat16 h, lo; bsplit(v, h, lo);
            a1h[m * 24 + k] = h; a1l[m * 24 + k] = lo;
        }
        copyg(sm + OFF_A3 + 12288, g_W1, 12288, tid);
    }
    __syncthreads();

    float acc[2][8][4];
    uint32_t ah[2][4], al[2][4], bh[4][4], bl[4][4];

    // ---- fc1: K=16, N=128 -> A2 ----
    zero_acc(acc);
    {
        #pragma unroll
        for (int i = 0; i < 2; i++) {
            int m = mb + i * 16 + r8 + ((mi & 1) << 3);
            int kb = (mi >> 1) << 4;
            ldsm4(A1h + m * 48 + kb, ah[i]);
            ldsm4(A1l + m * 48 + kb, al[i]);
        }
        #pragma unroll
        for (int p = 0; p < 4; p++) {
            int n = nb + p * 16 + r8 + ((mi >> 1) << 3);
            int kb = (mi & 1) << 4;
            ldsm4(W1h + n * 48 + kb, bh[p]);
            ldsm4(W1l + n * 48 + kb, bl[p]);
        }
        mma_tile(acc, ah, bh);
        mma_tile(acc, ah, bl);
        mma_tile(acc, al, bh);
    }
    epilogue_act(acc, A2h, A2l, 256, mb, nb, 0, fc1b, r4, c4);

    // ---- fc2: K=128, N=256 (2 n-halves x 2 k-chunks) -> A3 ----
    #pragma unroll 1
    for (int h = 0; h < 2; h++) {
        zero_acc(acc);
        #pragma unroll 1
        for (int c = 0; c < 2; c++) {
            __syncthreads();
            copyg(sm + OFF_WST,         g_W2 + (h * 2 + c) * 16384,        16384, tid);
            copyg(sm + OFF_WST + 16384, g_W2 + (h * 2 + c) * 16384 + 8192, 16384, tid);
            __syncthreads();
            #pragma unroll
            for (int ks = 0; ks < 4; ks++) {
                int kbA = (c * 64 + ks * 16) * 2;
                int kbW = (ks * 16) * 2;
                load_afrag(A2h, mb, kbA, 256, mi, r8, ah);
                load_afrag(A2l, mb, kbA, 256, mi, r8, al);
                load_bfrag(WST,         nb, kbW, 128, mi, r8, bh);
                load_bfrag(WST + 16384, nb, kbW, 128, mi, r8, bl);
                mma_tile(acc, ah, bh);
                mma_tile(acc, ah, bl);
                mma_tile(acc, al, bh);
            }
        }
        epilogue_act(acc, A3h, A3l, 512, mb, nb, h * 128, fc2b, r4, c4);
    }
    __syncthreads();

    // ---- fc3: K=256, N=128; W3 staged into A2 region (hi then lo) ----
    copyg(sm + OFF_A2, g_W3, 65536, tid);          // W3 hi
    __syncthreads();
    zero_acc(acc);
    #pragma unroll 1
    for (int ks = 0; ks < 16; ks++) {
        int kb = ks * 32;
        load_afrag(A3h, mb, kb, 512, mi, r8, ah);
        load_afrag(A3l, mb, kb, 512, mi, r8, al);
        load_bfrag(smb + OFF_A2, nb, kb, 512, mi, r8, bh);
        mma_tile(acc, ah, bh);
        mma_tile(acc, al, bh);
    }
    __syncthreads();
    copyg(sm + OFF_A2, g_W3 + 32768, 65536, tid);  // W3 lo
    __syncthreads();
    #pragma unroll 1
    for (int ks = 0; ks < 16; ks++) {
        int kb = ks * 32;
        load_afrag(A3h, mb, kb, 512, mi, r8, ah);
        load_bfrag(smb + OFF_A2, nb, kb, 512, mi, r8, bl);
        mma_tile(acc, ah, bl);
    }

    // ---- fc4: bias+relu+dot in regs, quad-shfl reduce, smem combine ----
    float part[4] = {0.f, 0.f, 0.f, 0.f};
    #pragma unroll
    for (int i = 0; i < 2; i++)
        #pragma unroll
        for (int j = 0; j < 8; j++) {
            int col = nb + j * 8 + c4 * 2;
            float b0 = __ldg(fc3b + col), b1 = __ldg(fc3b + col + 1);
            float w0 = __ldg(fc4w + col), w1 = __ldg(fc4w + col + 1);
            part[i * 2 + 0] += fmaxf(acc[i][j][0] + b0, 0.f) * w0
                             + fmaxf(acc[i][j][1] + b1, 0.f) * w1;
            part[i * 2 + 1] += fmaxf(acc[i][j][2] + b0, 0.f) * w0
                             + fmaxf(acc[i][j][3] + b1, 0.f) * w1;
        }
    #pragma unroll
    for (int q = 0; q < 4; q++) {
        part[q] += __shfl_xor_sync(0xffffffff, part[q], 1);
        part[q] += __shfl_xor_sync(0xffffffff, part[q], 2);
    }
    float* red = (float*)(sm + OFF_WST);
    __syncthreads();
    if (c4 == 0) {
        #pragma unroll
        for (int i = 0; i < 2; i++) {
            red[wn * 128 + mb + i * 16 + r4]     = part[i * 2];
            red[wn * 128 + mb + i * 16 + r4 + 8] = part[i * 2 + 1];
        }
    }
    __syncthreads();
    if (tid < 128) {
        float v = red[tid] + red[128 + tid] + __ldg(fc4b);
        int m = m0 + tid, p = m >> 8;
        if ((p >> 5) == (p & 31)) v = 0.f;
        g_preds[m] = v;
    }
}

// =====================================================================
// Kernel 3: 3-step propagation, block per p. Deterministic.
// =====================================================================
__global__ void __launch_bounds__(256) prop_kernel(const int* __restrict__ edges)
{
    __shared__ float xs[32];
    __shared__ float xn[8][32];
    __shared__ float acc[32];
    __shared__ float pr[256];
    __shared__ int   su[256], sv[256];
    int tid = threadIdx.x;
    int p = blockIdx.x;
    int s = p >> 5, t = p & 31;
    pr[tid] = g_preds[p * 256 + tid];
    su[tid] = edges[2 * tid];
    sv[tid] = edges[2 * tid + 1];
    if (tid < 32) { xs[tid] = (tid == s) ? 1.0f : 0.0f; acc[tid] = 0.0f; }
    __syncthreads();
    if (s != t) {
        int j = tid & 31, grp = tid >> 5;
        for (int step = 0; step < 3; step++) {
            float sum = 0.0f;
            #pragma unroll 4
            for (int q = 0; q < 32; q++) {
                int e = grp * 32 + q;
                sum += (sv[e] == j) ? xs[su[e]] * pr[e] : 0.0f;
            }
            xn[grp][j] = sum;
            __syncthreads();
            if (tid < 32) {
                float v = 0.0f;
                #pragma unroll
                for (int g2 = 0; g2 < 8; g2++) v += xn[g2][tid];
                xs[tid] = v;
                acc[tid] += v;
            }
            __syncthreads();
        }
    }
    if (tid < 32) g_part[p * 32 + tid] = acc[tid];
}

// =====================================================================
// Kernel 4: final reduction + normalize.
// =====================================================================
__global__ void __launch_bounds__(1024) reduce_kernel(float* __restrict__ out)
{
    __shared__ float red[32][32];
    __shared__ float rbc[32];
    __shared__ float tot;
    int tid = threadIdx.x;
    int j = tid & 31, chunk = tid >> 5;
    float sum = 0.0f;
    for (int q = 0; q < 32; q++)
        sum += g_part[(chunk * 32 + q) * 32 + j];
    red[chunk][j] = sum;
    __syncthreads();
    if (tid < 32) {
        float v = 0.0f;
        for (int c = 0; c < 32; c++) v += red[c][tid];
        rbc[tid] = v;
    }
    __syncthreads();
    if (tid == 0) {
        float tt = 0.0f;
        for (int k = 0; k < 32; k++) tt += rbc[k];
        tot = tt;
    }
    __syncthreads();
    if (tid < 32) out[tid] = rbc[tid] / tot;
}

// =====================================================================
extern "C" void kernel_launch(void* const* d_in, const int* in_sizes, int n_in,
                              void* d_out, int out_size)
{
    const float* emb   = (const float*)d_in[0];
    const int*   edges = (const int*)  d_in[1];
    const float* w1    = (const float*)d_in[2];
    const float* b1    = (const float*)d_in[3];
    const float* w2    = (const float*)d_in[4];
    const float* b2    = (const float*)d_in[5];
    const float* w3    = (const float*)d_in[6];
    const float* b3    = (const float*)d_in[7];
    const float* fc1w  = (const float*)d_in[8];
    const float* fc1b  = (const float*)d_in[9];
    const float* fc2w  = (const float*)d_in[10];
    const float* fc2b  = (const float*)d_in[11];
    const float* fc3w  = (const float*)d_in[12];
    const float* fc3b  = (const float*)d_in[13];
    const float* fc4w  = (const float*)d_in[14];
    const float* fc4b  = (const float*)d_in[15];

    prep_kernel<<<268, 256>>>(fc1w, fc2w, fc3w);
    conv_kernel<<<M_TOT / 256, 256>>>(emb, edges, w1, b1, w2, b2, w3, b3);

    cudaFuncSetAttribute(fc_kernel, cudaFuncAttributeMaxDynamicSharedMemorySize, FC_SMEM);
    fc_kernel<<<M_TOT / 128, 256, FC_SMEM>>>(fc1b, fc2b, fc3b, fc4w, fc4b);

    prop_kernel<<<P_PAIRS, 256>>>(edges);
    reduce_kernel<<<1, 1024>>>((float*)d_out);
}

// round 5
// speedup vs baseline: 2.7000x; 1.3584x over previous
#include <cuda_runtime.h>
#include <cuda_bf16.h>
#include <cstdint>

#define N_NODES 32
#define D_EMB   96
#define P_PAIRS 1024
#define M_TOT   262144   // P_PAIRS * 256

// ---- scratch (device globals: no allocations allowed) ----
__device__ float g_G[16 * M_TOT];       // conv features [feature][sample]
__device__ float g_preds[M_TOT];
__device__ float g_part[P_PAIRS * 32];
// weight images: bf16 hi/lo, pre-transposed [n][k], pre-swizzled (W2/W3)
__device__ __align__(16) __nv_bfloat16 g_W1[6144];    // [n=128][kp=24] hi | lo
__device__ __align__(16) __nv_bfloat16 g_W2[131072];  // 8 pieces of 8192: (h,c)->hi,lo
__device__ __align__(16) __nv_bfloat16 g_W3[65536];   // 4 pieces of 16384: (kh)->hi,lo

// ---------------- helpers ----------------
__device__ __forceinline__ uint32_t smem_u32(const void* p) {
    uint32_t a;
    asm("{ .reg .u64 t; cvta.to.shared.u64 t, %1; cvt.u32.u64 %0, t; }" : "=r"(a) : "l"(p));
    return a;
}
__device__ __forceinline__ uint32_t swz(int m, int kb, int rowb) {
    return (uint32_t)(m * rowb + (kb ^ ((m & 7) << 4)));
}
__device__ __forceinline__ void ldsm4(uint32_t a, uint32_t* r) {
    asm volatile("ldmatrix.sync.aligned.m8n8.x4.shared.b16 {%0,%1,%2,%3}, [%4];"
        : "=r"(r[0]), "=r"(r[1]), "=r"(r[2]), "=r"(r[3]) : "r"(a));
}
__device__ __forceinline__ void mma16816(float* c, const uint32_t* a, uint32_t b0, uint32_t b1) {
    asm volatile("mma.sync.aligned.m16n8k16.row.col.f32.bf16.bf16.f32 "
        "{%0,%1,%2,%3}, {%4,%5,%6,%7}, {%8,%9}, {%0,%1,%2,%3};"
        : "+f"(c[0]), "+f"(c[1]), "+f"(c[2]), "+f"(c[3])
        : "r"(a[0]), "r"(a[1]), "r"(a[2]), "r"(a[3]), "r"(b0), "r"(b1));
}
__device__ __forceinline__ void bsplit(float x, __nv_bfloat16& h, __nv_bfloat16& l) {
    h = __float2bfloat16_rn(x);
    l = __float2bfloat16_rn(x - __bfloat162float(h));
}
__device__ __forceinline__ uint32_t pk(__nv_bfloat16 lo, __nv_bfloat16 hi) {
    return (uint32_t)__bfloat16_as_ushort(hi) << 16 | (uint32_t)__bfloat16_as_ushort(lo);
}
__device__ __forceinline__ void sts32(uint32_t addr, uint32_t v) {
    asm volatile("st.shared.b32 [%0], %1;" :: "r"(addr), "r"(v) : "memory");
}
__device__ __forceinline__ void copyg(void* dst, const __nv_bfloat16* src, int bytes, int tid) {
    float4* d = (float4*)dst; const float4* s = (const float4*)src;
    for (int i = tid; i < (bytes >> 4); i += 256) d[i] = s[i];
}
// ---- cp.async (LDGSTS) ----
__device__ __forceinline__ void cpa16(uint32_t saddr, const void* g) {
    asm volatile("cp.async.cg.shared.global [%0], [%1], 16;" :: "r"(saddr), "l"(g) : "memory");
}
#define CP_COMMIT() asm volatile("cp.async.commit_group;" ::: "memory")
#define CP_WAIT0()  asm volatile("cp.async.wait_group 0;" ::: "memory")
__device__ __forceinline__ void stage16k(uint32_t sbuf, const __nv_bfloat16* src, int tid) {
    #pragma unroll
    for (int i = 0; i < 4; i++) {
        int idx = tid + i * 256;
        cpa16(sbuf + idx * 16, (const char*)src + idx * 16);
    }
}
__device__ __forceinline__ void stage32k(uint32_t sbuf, const __nv_bfloat16* src, int tid) {
    #pragma unroll
    for (int i = 0; i < 8; i++) {
        int idx = tid + i * 256;
        cpa16(sbuf + idx * 16, (const char*)src + idx * 16);
    }
}

// =====================================================================
// Kernel 0: prep — split weights to bf16 hi/lo images
// =====================================================================
__global__ void __launch_bounds__(256) prep_kernel(
    const float* __restrict__ fc1w, const float* __restrict__ fc2w,
    const float* __restrict__ fc3w)
{
    int idx = blockIdx.x * 256 + threadIdx.x;   // 0 .. 68607
    if (idx < 3072) {                 // W1: [n=128][kp=24], linear (padded)
        int n = idx / 24, k = idx % 24;
        float val = (k < 16) ? fc1w[k * 128 + n] : 0.0f;
        __nv_bfloat16 hh, ll; bsplit(val, hh, ll);
        g_W1[n * 24 + k] = hh; g_W1[3072 + n * 24 + k] = ll;
    } else if (idx < 35840) {         // W2: pieces [(h*2+c)]: hi 8192 | lo 8192, rowb=128
        int j = idx - 3072;
        int h = j >> 14, c = (j >> 13) & 1;
        int j2 = j & 8191;
        int n = j2 >> 6, k = j2 & 63;
        float val = fc2w[(c * 64 + k) * 256 + h * 128 + n];
        int eo = n * 64 + (((k * 2) ^ ((n & 7) << 4)) >> 1);
        int ph = (h * 2 + c) * 16384 + eo;
        __nv_bfloat16 hh, ll; bsplit(val, hh, ll);
        g_W2[ph] = hh; g_W2[ph + 8192] = ll;
    } else {                          // W3: k-halves, [128n][128k] rowb=256 swizzle
        int j = idx - 35840;          // 0..32767
        int n = j >> 8, k = j & 255;
        int kh = k >> 7, kl = k & 127;
        float val = fc3w[k * 128 + n];
        int eo = n * 128 + (((kl * 2) ^ ((n & 7) << 4)) >> 1);
        int ph = kh * 32768 + eo;
        __nv_bfloat16 hh, ll; bsplit(val, hh, ll);
        g_W3[ph] = hh; g_W3[ph + 16384] = ll;
    }
}

// =====================================================================
// Kernel 1: conv stack (thread per sample). Skips s==t blocks.
// =====================================================================
__global__ void __launch_bounds__(256) conv_kernel(
    const float* __restrict__ emb, const int* __restrict__ edges,
    const float* __restrict__ w1, const float* __restrict__ b1,
    const float* __restrict__ w2, const float* __restrict__ b2,
    const float* __restrict__ w3, const float* __restrict__ b3)
{
    int p = blockIdx.x;
    int s = p >> 5, t = p & 31;
    if (s == t) return;               // fc skips these tiles; output unused

    __shared__ float semb[N_NODES * D_EMB];
    __shared__ float sw1[48], sw2[48], sw3[48];
    __shared__ float sb1[4], sb2[4], sb3[4];
    int tid = threadIdx.x;
    for (int i = tid; i < N_NODES * D_EMB; i += 256) semb[i] = emb[i];
    if (tid < 48) { sw1[tid] = w1[tid]; sw2[tid] = w2[tid]; sw3[tid] = w3[tid]; }
    if (tid < 4)  { sb1[tid] = b1[tid]; sb2[tid] = b2[tid]; sb3[tid] = b3[tid]; }
    __syncthreads();

    int m = blockIdx.x * 256 + tid;
    int e = m & 255;
    int u = edges[2 * e], v = edges[2 * e + 1];
    const float* Xp[4] = { semb + s * D_EMB, semb + t * D_EMB,
                           semb + u * D_EMB, semb + v * D_EMB };

    float p1[4][23];
    #pragma unroll
    for (int i = 0; i < 23; i++) {
        float xw[4][5];
        #pragma unroll
        for (int c = 0; c < 4; c++)
            #pragma unroll
            for (int q = 0; q < 5; q++) xw[c][q] = Xp[c][4 * i + q];
        #pragma unroll
        for (int o = 0; o < 4; o++) {
            float a0 = sb1[o], a1 = sb1[o];
            #pragma unroll
            for (int c = 0; c < 4; c++)
                #pragma unroll
                for (int k = 0; k < 3; k++) {
                    float wv = sw1[(o * 4 + c) * 3 + k];
                    a0 = fmaf(wv, xw[c][k],     a0);
                    a1 = fmaf(wv, xw[c][k + 2], a1);
                }
            p1[o][i] = fmaxf(fmaxf(a0, a1), 0.0f);
        }
    }
    float p2[4][10];
    #pragma unroll
    for (int i = 0; i < 10; i++) {
        #pragma unroll
        for (int o = 0; o < 4; o++) {
            float a0 = sb2[o], a1 = sb2[o];
            #pragma unroll
            for (int c = 0; c < 4; c++)
                #pragma unroll
                for (int k = 0; k < 3; k++) {
                    float wv = sw2[(o * 4 + c) * 3 + k];
                    a0 = fmaf(wv, p1[c][2 * i + k],     a0);
                    a1 = fmaf(wv, p1[c][2 * i + 1 + k], a1);
                }
            p2[o][i] = fmaxf(fmaxf(a0, a1), 0.0f);
        }
    }
    #pragma unroll
    for (int pos = 0; pos < 4; pos++) {
        #pragma unroll
        for (int o = 0; o < 4; o++) {
            float a0 = sb3[o], a1 = sb3[o];
            #pragma unroll
            for (int c = 0; c < 4; c++)
                #pragma unroll
                for (int k = 0; k < 3; k++) {
                    float wv = sw3[(o * 4 + c) * 3 + k];
                    a0 = fmaf(wv, p2[c][2 * pos + k],     a0);
                    a1 = fmaf(wv, p2[c][2 * pos + 1 + k], a1);
                }
            g_G[(o * 4 + pos) * M_TOT + m] = fmaxf(fmaxf(a0, a1), 0.0f);
        }
    }
}

// =====================================================================
// Kernel 2: fused FC chain on HMMA, cp.async double-buffered staging.
// smem map: OFF_A2 0:64K (A2 hi|lo; later W3 ping-pong)
//           OFF_A3 64K:192K (A1+W1 at start; A3 hi|lo)
//           OFF_WST 192K:224K (W2 ping-pong 2x16K; later reduce buf)
// =====================================================================
#define OFF_A2  0
#define OFF_A3  65536
#define OFF_WST 196608
#define FC_SMEM 229376

__device__ __forceinline__ void zero_acc(float acc[2][8][4]) {
    #pragma unroll
    for (int i = 0; i < 2; i++)
        #pragma unroll
        for (int j = 0; j < 8; j++)
            #pragma unroll
            for (int q = 0; q < 4; q++) acc[i][j][q] = 0.f;
}
__device__ __forceinline__ void mma_tile(float acc[2][8][4],
                                         uint32_t a[2][4], uint32_t b[4][4]) {
    #pragma unroll
    for (int i = 0; i < 2; i++)
        #pragma unroll
        for (int p = 0; p < 4; p++) {
            mma16816(acc[i][2 * p],     a[i], b[p][0], b[p][1]);
            mma16816(acc[i][2 * p + 1], a[i], b[p][2], b[p][3]);
        }
}
__device__ __forceinline__ void load_afrag(uint32_t base, int mb, int kb0, int rowb,
                                           int mi, int r8, uint32_t a[2][4]) {
    #pragma unroll
    for (int i = 0; i < 2; i++) {
        int m = mb + i * 16 + r8 + ((mi & 1) << 3);
        int kb = kb0 + ((mi >> 1) << 4);
        ldsm4(base + swz(m, kb, rowb), a[i]);
    }
}
__device__ __forceinline__ void load_bfrag(uint32_t base, int nb, int kb0, int rowb,
                                           int mi, int r8, uint32_t b[4][4]) {
    #pragma unroll
    for (int p = 0; p < 4; p++) {
        int n = nb + p * 16 + r8 + ((mi >> 1) << 3);
        int kb = kb0 + ((mi & 1) << 4);
        ldsm4(base + swz(n, kb, rowb), b[p]);
    }
}
__device__ __forceinline__ void store_pair(uint32_t hib, uint32_t lob, int m, int col,
                                           int rowb, float v0, float v1) {
    __nv_bfloat16 h0, l0, h1, l1;
    bsplit(v0, h0, l0); bsplit(v1, h1, l1);
    uint32_t off = swz(m, col * 2, rowb);
    sts32(hib + off, pk(h0, h1));
    sts32(lob + off, pk(l0, l1));
}
__device__ __forceinline__ void epilogue_act(float acc[2][8][4],
    uint32_t hib, uint32_t lob, int rowb, int mb, int nb, int kofs,
    const float* __restrict__ bias, int r4, int c4)
{
    #pragma unroll
    for (int i = 0; i < 2; i++)
        #pragma unroll
        for (int j = 0; j < 8; j++) {
            int col = nb + j * 8 + c4 * 2;
            int dc = kofs + col;
            float b0 = __ldg(bias + dc), b1 = __ldg(bias + dc + 1);
            int m = mb + i * 16 + r4;
            store_pair(hib, lob, m, dc, rowb,
                       fmaxf(acc[i][j][0] + b0, 0.f), fmaxf(acc[i][j][1] + b1, 0.f));
            store_pair(hib, lob, m + 8, dc, rowb,
                       fmaxf(acc[i][j][2] + b0, 0.f), fmaxf(acc[i][j][3] + b1, 0.f));
        }
}

__global__ void __launch_bounds__(256) fc_kernel(
    const float* __restrict__ fc1b, const float* __restrict__ fc2b,
    const float* __restrict__ fc3b, const float* __restrict__ fc4w,
    const float* __restrict__ fc4b)
{
    const int m0 = blockIdx.x * 128;
    const int pp = m0 >> 8;
    if ((pp >> 5) == (pp & 31)) return;   // masked tile: prop writes zeros itself

    extern __shared__ char sm[];
    const uint32_t smb = smem_u32(sm);
    const int tid = threadIdx.x;
    const int l = tid & 31, w = tid >> 5;
    const int wm = w & 3, wn = w >> 2;
    const int mb = wm * 32, nb = wn * 64;
    const int mi = l >> 3, r8 = l & 7;
    const int r4 = l >> 2, c4 = l & 3;

    const uint32_t A1h = smb + OFF_A3, A1l = A1h + 6144;
    const uint32_t W1h = A1h + 12288, W1l = A1h + 18432;
    const uint32_t A2h = smb + OFF_A2, A2l = A2h + 32768;
    const uint32_t A3h = smb + OFF_A3, A3l = A3h + 65536;
    const uint32_t WST = smb + OFF_WST;

    // pre-issue fc2 piece 0 into WST buf0 (hidden under fc1 staging/compute)
    stage16k(WST, g_W2, tid); CP_COMMIT();

    // ---- stage A1 (from g_G, padded kp=24) + W1 ----
    {
        __nv_bfloat16* a1h = (__nv_bfloat16*)(sm + OFF_A3);
        __nv_bfloat16* a1l = (__nv_bfloat16*)(sm + OFF_A3 + 6144);
        for (int idx = tid; idx < 2048; idx += 256) {
            int k = idx >> 7, m = idx & 127;
            float v = g_G[k * M_TOT + m0 + m];
            __nv_bfloat16 h, lo; bsplit(v, h, lo);
            a1h[m * 24 + k] = h; a1l[m * 24 + k] = lo;
        }
        copyg(sm + OFF_A3 + 12288, g_W1, 12288, tid);
    }
    __syncthreads();

    float acc[2][8][4];
    uint32_t ah[2][4], al[2][4], bh[4][4], bl[4][4];

    // ---- fc1: K=16, N=128 -> A2 ----
    zero_acc(acc);
    {
        #pragma unroll
        for (int i = 0; i < 2; i++) {
            int m = mb + i * 16 + r8 + ((mi & 1) << 3);
            int kb = (mi >> 1) << 4;
            ldsm4(A1h + m * 48 + kb, ah[i]);
            ldsm4(A1l + m * 48 + kb, al[i]);
        }
        #pragma unroll
        for (int p = 0; p < 4; p++) {
            int n = nb + p * 16 + r8 + ((mi >> 1) << 3);
            int kb = (mi & 1) << 4;
            ldsm4(W1h + n * 48 + kb, bh[p]);
            ldsm4(W1l + n * 48 + kb, bl[p]);
        }
        mma_tile(acc, ah, bh);
        mma_tile(acc, ah, bl);
        mma_tile(acc, al, bh);
    }
    epilogue_act(acc, A2h, A2l, 256, mb, nb, 0, fc1b, r4, c4);

    // ---- fc2: K=128, N=256. 8 pipelined pieces of 16KB: (h,c)->hi,lo ----
    #pragma unroll 1
    for (int ip = 0; ip < 8; ip++) {
        CP_WAIT0();
        __syncthreads();     // piece ip visible; all warps done with piece ip-1
        if (ip < 7) { stage16k(WST + ((ip + 1) & 1) * 16384, g_W2 + (ip + 1) * 8192, tid); CP_COMMIT(); }
        const int h = ip >> 2, c = (ip >> 1) & 1, term = ip & 1;
        if ((ip & 3) == 0) zero_acc(acc);
        const uint32_t wb = WST + (ip & 1) * 16384;
        #pragma unroll
        for (int ks = 0; ks < 4; ks++) {
            int kbA = (c * 64 + ks * 16) * 2;
            int kbW = ks * 32;
            if (term == 0) {
                load_afrag(A2h, mb, kbA, 256, mi, r8, ah);
                load_afrag(A2l, mb, kbA, 256, mi, r8, al);
                load_bfrag(wb, nb, kbW, 128, mi, r8, bh);
                mma_tile(acc, ah, bh);
                mma_tile(acc, al, bh);
            } else {
                load_afrag(A2h, mb, kbA, 256, mi, r8, ah);
                load_bfrag(wb, nb, kbW, 128, mi, r8, bl);
                mma_tile(acc, ah, bl);
            }
        }
        if (ip == 3) epilogue_act(acc, A3h, A3l, 512, mb, nb, 0,   fc2b, r4, c4);
        if (ip == 7) epilogue_act(acc, A3h, A3l, 512, mb, nb, 128, fc2b, r4, c4);
    }
    __syncthreads();   // all warps done reading A2 + fc2 epilogue written

    // ---- fc3: K=256, N=128. 4 pipelined pieces of 32KB in A2 region ----
    stage32k(smb + OFF_A2, g_W3, tid); CP_COMMIT();
    zero_acc(acc);
    #pragma unroll 1
    for (int ip = 0; ip < 4; ip++) {
        CP_WAIT0();
        __syncthreads();
        if (ip < 3) { stage32k(smb + OFF_A2 + ((ip + 1) & 1) * 32768, g_W3 + (ip + 1) * 16384, tid); CP_COMMIT(); }
        const int kh = ip >> 1, term = ip & 1;
        const uint32_t wb = smb + OFF_A2 + (ip & 1) * 32768;
        #pragma unroll
        for (int ks = 0; ks < 8; ks++) {
            int kbA = (kh * 128 + ks * 16) * 2;
            int kbW = ks * 32;
            if (term == 0) {
                load_afrag(A3h, mb, kbA, 512, mi, r8, ah);
                load_afrag(A3l, mb, kbA, 512, mi, r8, al);
                load_bfrag(wb, nb, kbW, 256, mi, r8, bh);
                mma_tile(acc, ah, bh);
                mma_tile(acc, al, bh);
            } else {
                load_afrag(A3h, mb, kbA, 512, mi, r8, ah);
                load_bfrag(wb, nb, kbW, 256, mi, r8, bl);
                mma_tile(acc, ah, bl);
            }
        }
    }

    // ---- fc4: bias+relu+dot in regs, quad-shfl reduce, smem combine ----
    float part[4] = {0.f, 0.f, 0.f, 0.f};
    #pragma unroll
    for (int i = 0; i < 2; i++)
        #pragma unroll
        for (int j = 0; j < 8; j++) {
            int col = nb + j * 8 + c4 * 2;
            float b0 = __ldg(fc3b + col), b1 = __ldg(fc3b + col + 1);
            float w0 = __ldg(fc4w + col), w1 = __ldg(fc4w + col + 1);
            part[i * 2 + 0] += fmaxf(acc[i][j][0] + b0, 0.f) * w0
                             + fmaxf(acc[i][j][1] + b1, 0.f) * w1;
            part[i * 2 + 1] += fmaxf(acc[i][j][2] + b0, 0.f) * w0
                             + fmaxf(acc[i][j][3] + b1, 0.f) * w1;
        }
    #pragma unroll
    for (int q = 0; q < 4; q++) {
        part[q] += __shfl_xor_sync(0xffffffff, part[q], 1);
        part[q] += __shfl_xor_sync(0xffffffff, part[q], 2);
    }
    float* red = (float*)(sm + OFF_WST);
    __syncthreads();
    if (c4 == 0) {
        #pragma unroll
        for (int i = 0; i < 2; i++) {
            red[wn * 128 + mb + i * 16 + r4]     = part[i * 2];
            red[wn * 128 + mb + i * 16 + r4 + 8] = part[i * 2 + 1];
        }
    }
    __syncthreads();
    if (tid < 128) {
        float v = red[tid] + red[128 + tid] + __ldg(fc4b);
        g_preds[m0 + tid] = v;
    }
}

// =====================================================================
// Kernel 3: 3-step propagation, block per p. Deterministic.
// =====================================================================
__global__ void __launch_bounds__(256) prop_kernel(const int* __restrict__ edges)
{
    __shared__ float xs[32];
    __shared__ float xn[8][32];
    __shared__ float acc[32];
    __shared__ float pr[256];
    __shared__ int   su[256], sv[256];
    int tid = threadIdx.x;
    int p = blockIdx.x;
    int s = p >> 5, t = p & 31;
    su[tid] = edges[2 * tid];
    sv[tid] = edges[2 * tid + 1];
    if (s != t) pr[tid] = g_preds[p * 256 + tid];
    if (tid < 32) { xs[tid] = (tid == s) ? 1.0f : 0.0f; acc[tid] = 0.0f; }
    __syncthreads();
    if (s != t) {
        int j = tid & 31, grp = tid >> 5;
        for (int step = 0; step < 3; step++) {
            float sum = 0.0f;
            #pragma unroll 4
            for (int q = 0; q < 32; q++) {
                int e = grp * 32 + q;
                sum += (sv[e] == j) ? xs[su[e]] * pr[e] : 0.0f;
            }
            xn[grp][j] = sum;
            __syncthreads();
            if (tid < 32) {
                float v = 0.0f;
                #pragma unroll
                for (int g2 = 0; g2 < 8; g2++) v += xn[g2][tid];
                xs[tid] = v;
                acc[tid] += v;
            }
            __syncthreads();
        }
    }
    if (tid < 32) g_part[p * 32 + tid] = acc[tid];
}

// =====================================================================
// Kernel 4: final reduction + normalize.
// =====================================================================
__global__ void __launch_bounds__(1024) reduce_kernel(float* __restrict__ out)
{
    __shared__ float red[32][32];
    __shared__ float rbc[32];
    __shared__ float tot;
    int tid = threadIdx.x;
    int j = tid & 31, chunk = tid >> 5;
    float sum = 0.0f;
    for (int q = 0; q < 32; q++)
        sum += g_part[(chunk * 32 + q) * 32 + j];
    red[chunk][j] = sum;
    __syncthreads();
    if (tid < 32) {
        float v = 0.0f;
        for (int c = 0; c < 32; c++) v += red[c][tid];
        rbc[tid] = v;
    }
    __syncthreads();
    if (tid == 0) {
        float tt = 0.0f;
        for (int k = 0; k < 32; k++) tt += rbc[k];
        tot = tt;
    }
    __syncthreads();
    if (tid < 32) out[tid] = rbc[tid] / tot;
}

// =====================================================================
extern "C" void kernel_launch(void* const* d_in, const int* in_sizes, int n_in,
                              void* d_out, int out_size)
{
    const float* emb   = (const float*)d_in[0];
    const int*   edges = (const int*)  d_in[1];
    const float* w1    = (const float*)d_in[2];
    const float* b1    = (const float*)d_in[3];
    const float* w2    = (const float*)d_in[4];
    const float* b2    = (const float*)d_in[5];
    const float* w3    = (const float*)d_in[6];
    const float* b3    = (const float*)d_in[7];
    const float* fc1w  = (const float*)d_in[8];
    const float* fc1b  = (const float*)d_in[9];
    const float* fc2w  = (const float*)d_in[10];
    const float* fc2b  = (const float*)d_in[11];
    const float* fc3w  = (const float*)d_in[12];
    const float* fc3b  = (const float*)d_in[13];
    const float* fc4w  = (const float*)d_in[14];
    const float* fc4b  = (const float*)d_in[15];

    prep_kernel<<<268, 256>>>(fc1w, fc2w, fc3w);
    conv_kernel<<<P_PAIRS, 256>>>(emb, edges, w1, b1, w2, b2, w3, b3);

    cudaFuncSetAttribute(fc_kernel, cudaFuncAttributeMaxDynamicSharedMemorySize, FC_SMEM);
    fc_kernel<<<M_TOT / 128, 256, FC_SMEM>>>(fc1b, fc2b, fc3b, fc4w, fc4b);

    prop_kernel<<<P_PAIRS, 256>>>(edges);
    reduce_kernel<<<1, 1024>>>((float*)d_out);
}